// round 6
// baseline (speedup 1.0000x reference)
#include <cuda_runtime.h>
#include <cstdint>

// Izhikevich neuron simulation on GB300 — round 5.
// 512 CTAs x 256 threads (8 warps), each CTA owns 32 sequences.
// Roles rotated across physical warps per CTA (SMSP load balance):
//   rwid 0: compute (serial chain, SMEM->SMEM)
//   rwid 1: producer (cp.async GMEM->SMEM, double buffered)
//   rwid 2-7: store warps, 3 streams x 2 time-halves (10 STG each)

#define BATCH    32
#define NSTEPS   2000
#define NNEUR    512
#define PLANE    (NSTEPS * NNEUR)
#define NTOT     (BATCH * PLANE)
#define CHUNK    20
#define HALF     (CHUNK / 2)
#define NCHUNKS  (NSTEPS / CHUNK)        // 100
#define CHEL     (CHUNK * NNEUR)

__device__ __forceinline__ void cp_async4(uint32_t saddr, const float* __restrict__ g)
{
    asm volatile("cp.async.ca.shared.global [%0], [%1], 4;"
                 :: "r"(saddr), "l"(g) : "memory");
}
__device__ __forceinline__ void cp_commit()
{
    asm volatile("cp.async.commit_group;" ::: "memory");
}
__device__ __forceinline__ void cp_wait0()
{
    asm volatile("cp.async.wait_group 0;" ::: "memory");
}

__global__ __launch_bounds__(256, 4)
void izhikevich_kernel(const float* __restrict__ in,
                       float* __restrict__ out_s,
                       float* __restrict__ out_v,
                       float* __restrict__ out_u)
{
    __shared__ float s_in[2][CHUNK][32];
    __shared__ float s_s [2][CHUNK][32];
    __shared__ float s_v [2][CHUNK][32];
    __shared__ float s_u [2][CHUNK][32];

    const int wid  = threadIdx.x >> 5;
    const int lane = threadIdx.x & 31;
    const int rwid = (wid + (int)blockIdx.x) & 7;   // rotated role id
    const int seq  = blockIdx.x * 32 + lane;
    const int b    = seq >> 9;
    const int n    = seq & 511;
    const int base = b * PLANE + n;

    const float* __restrict__ ip = in + base;

    float v = -65.0f;
    float u = -13.0f;   // B * C

    // ---- prologue: producer fills buffer 0 ----
    if (rwid == 1) {
        #pragma unroll
        for (int j = 0; j < CHUNK; ++j)
            cp_async4((uint32_t)__cvta_generic_to_shared(&s_in[0][j][lane]),
                      ip + j * NNEUR);
        cp_commit();
        cp_wait0();
    }
    __syncthreads();

    #pragma unroll 1
    for (int k = 0; k < NCHUNKS; ++k) {
        const int p = k & 1;

        if (rwid == 0) {
            // ---- compute chunk k (serial chain; exact reference order) ----
            #pragma unroll
            for (int j = 0; j < CHUNK; ++j) {
                float i_t = s_in[p][j][lane];
                float dv = (0.04f * v * v + 5.0f * v + 140.0f - u + i_t) * 0.5f;
                float du = (0.02f * (0.2f * v - u)) * 0.5f;
                v = v + dv;
                u = u + du;
                bool  fired = (v >= 30.0f);
                float s = fired ? 1.0f : 0.0f;
                v = fired ? -65.0f : v;
                u = fired ? u + 8.0f : u;
                s_s[p][j][lane] = s;
                s_v[p][j][lane] = v;
                s_u[p][j][lane] = u;
            }
        } else if (rwid == 1) {
            // ---- producer: cp.async chunk k+1 into the other buffer ----
            if (k + 1 < NCHUNKS) {
                const float* q = ip + (k + 1) * CHEL;
                #pragma unroll
                for (int j = 0; j < CHUNK; ++j)
                    cp_async4((uint32_t)__cvta_generic_to_shared(&s_in[p ^ 1][j][lane]),
                              q + j * NNEUR);
                cp_commit();
            }
        } else if (k >= 1) {
            // ---- store warps: drain chunk k-1; stream x half ----
            const int pm     = (k - 1) & 1;
            const int r      = rwid - 2;        // 0..5
            const int stream = r >> 1;          // 0:s 1:v 2:u
            const int half   = r & 1;
            const float (*buf)[32] =
                (stream == 0) ? s_s[pm] : (stream == 1) ? s_v[pm] : s_u[pm];
            float* __restrict__ g =
                ((stream == 0) ? out_s : (stream == 1) ? out_v : out_u)
                + base + (k - 1) * CHEL + half * HALF * NNEUR;
            #pragma unroll
            for (int j = 0; j < HALF; ++j)
                __stcs(g + j * NNEUR, buf[half * HALF + j][lane]);
        }

        if (rwid == 1)
            cp_wait0();     // chunk k+1 landed (hidden behind this iter's work)
        __syncthreads();
    }

    // ---- epilogue: drain final chunk ----
    if (rwid >= 2) {
        const int pm     = (NCHUNKS - 1) & 1;
        const int r      = rwid - 2;
        const int stream = r >> 1;
        const int half   = r & 1;
        const float (*buf)[32] =
            (stream == 0) ? s_s[pm] : (stream == 1) ? s_v[pm] : s_u[pm];
        float* __restrict__ g =
            ((stream == 0) ? out_s : (stream == 1) ? out_v : out_u)
            + base + (NCHUNKS - 1) * CHEL + half * HALF * NNEUR;
        #pragma unroll
        for (int j = 0; j < HALF; ++j)
            __stcs(g + j * NNEUR, buf[half * HALF + j][lane]);
    }
}

extern "C" void kernel_launch(void* const* d_in, const int* in_sizes, int n_in,
                              void* d_out, int out_size)
{
    const float* in = (const float*)d_in[0];
    float* out      = (float*)d_out;

    izhikevich_kernel<<<512, 256>>>(in, out, out + NTOT, out + 2 * NTOT);
}

// round 7
// speedup vs baseline: 1.0050x; 1.0050x over previous
#include <cuda_runtime.h>
#include <cstdint>

// Izhikevich neuron simulation on GB300 — round 5.
// 512 CTAs x 256 threads (8 warps), each CTA owns 32 sequences.
// Roles rotated across physical warps per CTA (SMSP load balance):
//   rwid 0: compute (serial chain, SMEM->SMEM)
//   rwid 1: producer (cp.async GMEM->SMEM, double buffered)
//   rwid 2-7: store warps, 3 streams x 2 time-halves (10 STG each)

#define BATCH    32
#define NSTEPS   2000
#define NNEUR    512
#define PLANE    (NSTEPS * NNEUR)
#define NTOT     (BATCH * PLANE)
#define CHUNK    20
#define HALF     (CHUNK / 2)
#define NCHUNKS  (NSTEPS / CHUNK)        // 100
#define CHEL     (CHUNK * NNEUR)

__device__ __forceinline__ void cp_async4(uint32_t saddr, const float* __restrict__ g)
{
    asm volatile("cp.async.ca.shared.global [%0], [%1], 4;"
                 :: "r"(saddr), "l"(g) : "memory");
}
__device__ __forceinline__ void cp_commit()
{
    asm volatile("cp.async.commit_group;" ::: "memory");
}
__device__ __forceinline__ void cp_wait0()
{
    asm volatile("cp.async.wait_group 0;" ::: "memory");
}

__global__ __launch_bounds__(256, 4)
void izhikevich_kernel(const float* __restrict__ in,
                       float* __restrict__ out_s,
                       float* __restrict__ out_v,
                       float* __restrict__ out_u)
{
    __shared__ float s_in[2][CHUNK][32];
    __shared__ float s_s [2][CHUNK][32];
    __shared__ float s_v [2][CHUNK][32];
    __shared__ float s_u [2][CHUNK][32];

    const int wid  = threadIdx.x >> 5;
    const int lane = threadIdx.x & 31;
    const int rwid = (wid + (int)blockIdx.x) & 7;   // rotated role id
    const int seq  = blockIdx.x * 32 + lane;
    const int b    = seq >> 9;
    const int n    = seq & 511;
    const int base = b * PLANE + n;

    const float* __restrict__ ip = in + base;

    float v = -65.0f;
    float u = -13.0f;   // B * C

    // ---- prologue: producer fills buffer 0 ----
    if (rwid == 1) {
        #pragma unroll
        for (int j = 0; j < CHUNK; ++j)
            cp_async4((uint32_t)__cvta_generic_to_shared(&s_in[0][j][lane]),
                      ip + j * NNEUR);
        cp_commit();
        cp_wait0();
    }
    __syncthreads();

    #pragma unroll 1
    for (int k = 0; k < NCHUNKS; ++k) {
        const int p = k & 1;

        if (rwid == 0) {
            // ---- compute chunk k (serial chain; exact reference order) ----
            #pragma unroll
            for (int j = 0; j < CHUNK; ++j) {
                float i_t = s_in[p][j][lane];
                float dv = (0.04f * v * v + 5.0f * v + 140.0f - u + i_t) * 0.5f;
                float du = (0.02f * (0.2f * v - u)) * 0.5f;
                v = v + dv;
                u = u + du;
                bool  fired = (v >= 30.0f);
                float s = fired ? 1.0f : 0.0f;
                v = fired ? -65.0f : v;
                u = fired ? u + 8.0f : u;
                s_s[p][j][lane] = s;
                s_v[p][j][lane] = v;
                s_u[p][j][lane] = u;
            }
        } else if (rwid == 1) {
            // ---- producer: cp.async chunk k+1 into the other buffer ----
            if (k + 1 < NCHUNKS) {
                const float* q = ip + (k + 1) * CHEL;
                #pragma unroll
                for (int j = 0; j < CHUNK; ++j)
                    cp_async4((uint32_t)__cvta_generic_to_shared(&s_in[p ^ 1][j][lane]),
                              q + j * NNEUR);
                cp_commit();
            }
        } else if (k >= 1) {
            // ---- store warps: drain chunk k-1; stream x half ----
            const int pm     = (k - 1) & 1;
            const int r      = rwid - 2;        // 0..5
            const int stream = r >> 1;          // 0:s 1:v 2:u
            const int half   = r & 1;
            const float (*buf)[32] =
                (stream == 0) ? s_s[pm] : (stream == 1) ? s_v[pm] : s_u[pm];
            float* __restrict__ g =
                ((stream == 0) ? out_s : (stream == 1) ? out_v : out_u)
                + base + (k - 1) * CHEL + half * HALF * NNEUR;
            #pragma unroll
            for (int j = 0; j < HALF; ++j)
                __stcs(g + j * NNEUR, buf[half * HALF + j][lane]);
        }

        if (rwid == 1)
            cp_wait0();     // chunk k+1 landed (hidden behind this iter's work)
        __syncthreads();
    }

    // ---- epilogue: drain final chunk ----
    if (rwid >= 2) {
        const int pm     = (NCHUNKS - 1) & 1;
        const int r      = rwid - 2;
        const int stream = r >> 1;
        const int half   = r & 1;
        const float (*buf)[32] =
            (stream == 0) ? s_s[pm] : (stream == 1) ? s_v[pm] : s_u[pm];
        float* __restrict__ g =
            ((stream == 0) ? out_s : (stream == 1) ? out_v : out_u)
            + base + (NCHUNKS - 1) * CHEL + half * HALF * NNEUR;
        #pragma unroll
        for (int j = 0; j < HALF; ++j)
            __stcs(g + j * NNEUR, buf[half * HALF + j][lane]);
    }
}

extern "C" void kernel_launch(void* const* d_in, const int* in_sizes, int n_in,
                              void* d_out, int out_size)
{
    const float* in = (const float*)d_in[0];
    float* out      = (float*)d_out;

    izhikevich_kernel<<<512, 256>>>(in, out, out + NTOT, out + 2 * NTOT);
}